// round 15
// baseline (speedup 1.0000x reference)
#include <cuda_runtime.h>
#include <math.h>

// Problem constants
#define BN   4
#define SN   512
#define DN   64
#define HN   8
#define FFN  128
#define EPSV 1e-5f

typedef unsigned long long u64;
typedef unsigned int u32;

// ---------------------------------------------------------------------------
// Packed fp32x2 helpers (sm_100+)
// ---------------------------------------------------------------------------
__device__ __forceinline__ u64 pack2(float lo, float hi) {
    u64 r; asm("mov.b64 %0, {%1, %2};" : "=l"(r) : "f"(lo), "f"(hi)); return r;
}
__device__ __forceinline__ u64 dup2(float x) {
    u64 r; asm("mov.b64 %0, {%1, %1};" : "=l"(r) : "f"(x)); return r;
}
__device__ __forceinline__ void ffma2(u64& d, u64 a, u64 b) {
    asm("fma.rn.f32x2 %0, %1, %2, %0;" : "+l"(d) : "l"(a), "l"(b));
}
__device__ __forceinline__ u64 addp2(u64 a, u64 b) {
    u64 r; asm("add.rn.f32x2 %0, %1, %2;" : "=l"(r) : "l"(a), "l"(b)); return r;
}
__device__ __forceinline__ float2 unpack2(u64 v) {
    float2 f; asm("mov.b64 {%0, %1}, %2;" : "=f"(f.x), "=f"(f.y) : "l"(v)); return f;
}

// ---------------------------------------------------------------------------
// tf32 MMA helpers (3xTF32 split)
// ---------------------------------------------------------------------------
__device__ __forceinline__ u32 tf32_of(float x) {
    u32 r; asm("cvt.rna.tf32.f32 %0, %1;" : "=r"(r) : "f"(x)); return r;
}
__device__ __forceinline__ void split_tf32(float x, u32& hi, u32& lo) {
    hi = tf32_of(x);
    lo = tf32_of(x - __uint_as_float(hi));
}
__device__ __forceinline__ void mma8(float* d, const u32* a, const u32* b) {
    asm volatile(
        "mma.sync.aligned.m16n8k8.row.col.f32.tf32.tf32.f32 "
        "{%0,%1,%2,%3}, {%4,%5,%6,%7}, {%8,%9}, {%0,%1,%2,%3};"
        : "+f"(d[0]), "+f"(d[1]), "+f"(d[2]), "+f"(d[3])
        : "r"(a[0]), "r"(a[1]), "r"(a[2]), "r"(a[3]), "r"(b[0]), "r"(b[1]));
}

// ---------------------------------------------------------------------------
// Scratch
// ---------------------------------------------------------------------------
__device__ float g_q[BN * HN * SN * DN];
__device__ float g_k[BN * HN * SN * DN];
__device__ float g_v[BN * HN * SN * DN];
__device__ float g_p[(size_t)BN * HN * SN * SN];
__device__ float g_heads[BN * SN * HN * DN];
__device__ float g_po[8][BN * SN * DN];           // proj K-split partials

// ---------------------------------------------------------------------------
// Kernel 1: FUSED posbias + qkv (R13, measured)
// ---------------------------------------------------------------------------
#define PB_BLOCKS (4 * SN * 4)
#define QKV_BLOCKS (32 * 8 * 3)
#define PREP_SMEM_FLOATS (128 * 65 + 64 * 8 + 8)

__global__ __launch_bounds__(256) void prep_kernel(
    const float* __restrict__ seq, const float* __restrict__ Wq,
    const float* __restrict__ Wk, const float* __restrict__ Wv,
    const float* __restrict__ pos, const float* __restrict__ Wp,
    const float* __restrict__ bp)
{
    __shared__ float smem_u[PREP_SMEM_FLOATS];
    const int tid = threadIdx.x;

    if (blockIdx.x < PB_BLOCKS) {
        float (*sP)[65] = reinterpret_cast<float(*)[65]>(smem_u);
        float (*sW)[8]  = reinterpret_cast<float(*)[8]>(smem_u + 128 * 65);
        float* sbp      = smem_u + 128 * 65 + 64 * 8;

        const int idx = blockIdx.x;
        const int jt  = idx & 3;
        const int i   = (idx >> 2) & 511;
        const int b   = idx >> 11;

        for (int k = tid; k < 512; k += 256) sW[k >> 3][k & 7] = Wp[k];
        if (tid < 8) sbp[tid] = bp[tid];

        const float* src = pos + (((size_t)b * SN + i) * SN + jt * 128) * DN;
        #pragma unroll
        for (int it = 0; it < 8; it++) {
            int id = tid + it * 256;
            int r = id >> 4, c = (id & 15) << 2;
            float4 v4 = __ldcs(reinterpret_cast<const float4*>(src + (size_t)r * 64 + c));
            sP[r][c] = v4.x; sP[r][c + 1] = v4.y; sP[r][c + 2] = v4.z; sP[r][c + 3] = v4.w;
        }
        __syncthreads();

        const int jr = tid & 127;
        const int hb = (tid >> 7) * 2;
        u64 acc[2];
        #pragma unroll
        for (int p = 0; p < 2; p++)
            acc[p] = pack2(sbp[2 * (hb + p)], sbp[2 * (hb + p) + 1]);
        #pragma unroll 16
        for (int d = 0; d < 64; d++) {
            u64 x = dup2(sP[jr][d]);
            #pragma unroll
            for (int p = 0; p < 2; p++) {
                u64 w = *reinterpret_cast<const u64*>(&sW[d][2 * (hb + p)]);
                ffma2(acc[p], x, w);
            }
        }

        const int j = jt * 128 + jr;
        #pragma unroll
        for (int p = 0; p < 2; p++) {
            float2 v = unpack2(acc[p]);
            int h0 = 2 * (hb + p);
            g_p[(((size_t)b * HN + h0) * SN + i) * SN + j]     = v.x;
            g_p[(((size_t)b * HN + h0 + 1) * SN + i) * SN + j] = v.y;
        }
    } else {
        float* sA = smem_u;
        float* sB = smem_u + 64 * 65;

        const int bx2  = blockIdx.x - PB_BLOCKS;
        const int m0   = (bx2 & 31) * 64;
        const int head = (bx2 >> 5) & 7;
        const int z    = bx2 >> 8;
        const float* __restrict__ W = (z == 0) ? Wq : (z == 1 ? Wk : Wv);
        float* outB = (z == 0) ? g_q : (z == 1 ? g_k : g_v);

        for (int idx = tid; idx < 64 * 16; idx += 256) {
            int r = idx >> 4, c = (idx & 15) << 2;
            float4 a4 = *reinterpret_cast<const float4*>(seq + (size_t)(m0 + r) * 64 + c);
            sA[r * 65 + c] = a4.x; sA[r * 65 + c + 1] = a4.y;
            sA[r * 65 + c + 2] = a4.z; sA[r * 65 + c + 3] = a4.w;
            float4 b4 = *reinterpret_cast<const float4*>(W + (size_t)r * 512 + head * 64 + c);
            sB[r * 66 + c] = b4.x; sB[r * 66 + c + 1] = b4.y;
            sB[r * 66 + c + 2] = b4.z; sB[r * 66 + c + 3] = b4.w;
        }
        __syncthreads();

        const int ty = tid >> 4, tx = tid & 15;
        u64 acc[4][2] = {};
        #pragma unroll 16
        for (int k = 0; k < 64; k++) {
            u64 b0 = *reinterpret_cast<const u64*>(&sB[k * 66 + tx * 4]);
            u64 b1 = *reinterpret_cast<const u64*>(&sB[k * 66 + tx * 4 + 2]);
            #pragma unroll
            for (int i = 0; i < 4; i++) {
                u64 a = dup2(sA[(ty * 4 + i) * 65 + k]);
                ffma2(acc[i][0], a, b0);
                ffma2(acc[i][1], a, b1);
            }
        }

        const int bb = m0 >> 9;
        const int s0 = m0 & 511;
        #pragma unroll
        for (int i = 0; i < 4; i++) {
            float2 p0 = unpack2(acc[i][0]), p1 = unpack2(acc[i][1]);
            float4 o4 = make_float4(p0.x, p0.y, p1.x, p1.y);
            *reinterpret_cast<float4*>(
                outB + ((size_t)((bb * HN + head) * SN + s0 + ty * 4 + i)) * DN + tx * 4) = o4;
        }
    }
}

// ---------------------------------------------------------------------------
// Kernel 3: attention + K/V register prefetch software pipeline: next jt's
// tile is LDG'd into registers before the MMA loop, so L2 latency overlaps
// the ~500-cycle MMA chain instead of being exposed at the sync.
// ---------------------------------------------------------------------------
#define AT_TI 32
#define QLD   68
#define KLD   68
#define VLD   72
#define SLD   516
#define ATTN_SMEM_FLOATS (AT_TI * QLD + 2 * 64 * VLD + AT_TI * SLD + AT_TI)
#define ATTN_SMEM_BYTES  (ATTN_SMEM_FLOATS * 4)

__global__ __launch_bounds__(256, 2) void attn_kernel()
{
    extern __shared__ float sm[];
    float* sQ   = sm;
    float* sKVh = sQ + AT_TI * QLD;
    float* sKVl = sKVh + 64 * VLD;
    float* sS   = sKVl + 64 * VLD;
    float* sInv = sS + AT_TI * SLD;

    const int bh  = blockIdx.x;
    const int i0  = blockIdx.y * AT_TI;
    const int tid = threadIdx.x;
    const int w    = tid >> 5, lane = tid & 31;
    const int mh   = (w & 1) * 16;
    const int nq   = (w >> 1) * 16;
    const int lr   = lane >> 2, lc = lane & 3;
    const int ldr  = tid >> 4, ldc = (tid & 15) << 2;   // tile-load coords

    const float* qsrc = g_q + ((size_t)bh * SN + i0) * DN;
    #pragma unroll
    for (int it = 0; it < 2; it++) {
        int id = tid + it * 256;
        int r = id >> 4, c = (id & 15) << 2;
        float4 v = *reinterpret_cast<const float4*>(qsrc + (size_t)r * 64 + c);
        sQ[r * QLD + c] = v.x; sQ[r * QLD + c + 1] = v.y;
        sQ[r * QLD + c + 2] = v.z; sQ[r * QLD + c + 3] = v.w;
    }
    __syncthreads();

    u32 qh[8][4], ql[8][4];
    #pragma unroll
    for (int k8 = 0; k8 < 8; k8++) {
        float a0 = sQ[(mh + lr) * QLD + k8 * 8 + lc];
        float a1 = sQ[(mh + lr + 8) * QLD + k8 * 8 + lc];
        float a2 = sQ[(mh + lr) * QLD + k8 * 8 + lc + 4];
        float a3 = sQ[(mh + lr + 8) * QLD + k8 * 8 + lc + 4];
        split_tf32(a0, qh[k8][0], ql[k8][0]);
        split_tf32(a1, qh[k8][1], ql[k8][1]);
        split_tf32(a2, qh[k8][2], ql[k8][2]);
        split_tf32(a3, qh[k8][3], ql[k8][3]);
    }
    const float* pbase = g_p + ((size_t)bh * SN + i0) * SN;
    const float* kbase = g_k + (size_t)bh * SN * DN;
    const float* vbase = g_v + (size_t)bh * SN * DN;

    // ---- Phase 1: S = QK^T * 0.125 + P  (register-pipelined K tiles)
    float4 kv[4];
    #pragma unroll
    for (int it = 0; it < 4; it++)
        kv[it] = *reinterpret_cast<const float4*>(
            kbase + (size_t)(ldr + it * 16) * 64 + ldc);

    for (int jt = 0; jt < 8; jt++) {
        __syncthreads();
        #pragma unroll
        for (int it = 0; it < 4; it++) {
            int r = ldr + it * 16;
            u32 h0, l0, h1, l1, h2, l2, h3, l3;
            split_tf32(kv[it].x, h0, l0); split_tf32(kv[it].y, h1, l1);
            split_tf32(kv[it].z, h2, l2); split_tf32(kv[it].w, h3, l3);
            *reinterpret_cast<uint4*>(&sKVh[r * KLD + ldc]) = make_uint4(h0, h1, h2, h3);
            *reinterpret_cast<uint4*>(&sKVl[r * KLD + ldc]) = make_uint4(l0, l1, l2, l3);
        }
        __syncthreads();

        if (jt < 7) {
            #pragma unroll
            for (int it = 0; it < 4; it++)
                kv[it] = *reinterpret_cast<const float4*>(
                    kbase + (size_t)((jt + 1) * 64 + ldr + it * 16) * 64 + ldc);
        }

        float2 pf[2][2];
        #pragma unroll
        for (int nt = 0; nt < 2; nt++) {
            int col = jt * 64 + nq + nt * 8 + 2 * lc;
            pf[nt][0] = *reinterpret_cast<const float2*>(
                pbase + (size_t)(mh + lr) * SN + col);
            pf[nt][1] = *reinterpret_cast<const float2*>(
                pbase + (size_t)(mh + lr + 8) * SN + col);
        }

        float D[2][4] = {};
        #pragma unroll
        for (int k8 = 0; k8 < 8; k8++) {
            #pragma unroll
            for (int nt = 0; nt < 2; nt++) {
                int base = (nq + nt * 8 + lr) * KLD + k8 * 8 + lc;
                u32 Bh[2] = { *reinterpret_cast<const u32*>(&sKVh[base]),
                              *reinterpret_cast<const u32*>(&sKVh[base + 4]) };
                u32 Bl[2] = { *reinterpret_cast<const u32*>(&sKVl[base]),
                              *reinterpret_cast<const u32*>(&sKVl[base + 4]) };
                mma8(D[nt], qh[k8], Bh);
                mma8(D[nt], ql[k8], Bh);
                mma8(D[nt], qh[k8], Bl);
            }
        }
        #pragma unroll
        for (int nt = 0; nt < 2; nt++) {
            int col = jt * 64 + nq + nt * 8 + 2 * lc;
            *reinterpret_cast<float2*>(&sS[(mh + lr) * SLD + col]) =
                make_float2(D[nt][0] * 0.125f + pf[nt][0].x,
                            D[nt][1] * 0.125f + pf[nt][0].y);
            *reinterpret_cast<float2*>(&sS[(mh + lr + 8) * SLD + col]) =
                make_float2(D[nt][2] * 0.125f + pf[nt][1].x,
                            D[nt][3] * 0.125f + pf[nt][1].y);
        }
    }
    __syncthreads();

    // ---- Phase 2: softmax
    #pragma unroll
    for (int rr = 0; rr < 4; rr++) {
        int r = w * 4 + rr;
        float* row = sS + r * SLD;
        float mx = -1e30f;
        #pragma unroll
        for (int c = 0; c < 16; c++) mx = fmaxf(mx, row[lane + c * 32]);
        #pragma unroll
        for (int off = 16; off > 0; off >>= 1)
            mx = fmaxf(mx, __shfl_xor_sync(0xffffffffu, mx, off));
        float sum = 0.f;
        #pragma unroll
        for (int c = 0; c < 16; c++) {
            float e = __expf(row[lane + c * 32] - mx);
            row[lane + c * 32] = e;
            sum += e;
        }
        #pragma unroll
        for (int off = 16; off > 0; off >>= 1)
            sum += __shfl_xor_sync(0xffffffffu, sum, off);
        if (lane == 0) sInv[r] = 1.f / sum;
    }
    __syncthreads();

    // ---- Phase 3: O = A @ V  (register-pipelined V tiles)
    #pragma unroll
    for (int it = 0; it < 4; it++)
        kv[it] = *reinterpret_cast<const float4*>(
            vbase + (size_t)(ldr + it * 16) * 64 + ldc);

    float O[2][4] = {};
    for (int jt = 0; jt < 8; jt++) {
        __syncthreads();
        #pragma unroll
        for (int it = 0; it < 4; it++) {
            int r = ldr + it * 16;
            u32 h0, l0, h1, l1, h2, l2, h3, l3;
            split_tf32(kv[it].x, h0, l0); split_tf32(kv[it].y, h1, l1);
            split_tf32(kv[it].z, h2, l2); split_tf32(kv[it].w, h3, l3);
            *reinterpret_cast<uint4*>(&sKVh[r * VLD + ldc]) = make_uint4(h0, h1, h2, h3);
            *reinterpret_cast<uint4*>(&sKVl[r * VLD + ldc]) = make_uint4(l0, l1, l2, l3);
        }
        __syncthreads();

        if (jt < 7) {
            #pragma unroll
            for (int it = 0; it < 4; it++)
                kv[it] = *reinterpret_cast<const float4*>(
                    vbase + (size_t)((jt + 1) * 64 + ldr + it * 16) * 64 + ldc);
        }

        #pragma unroll
        for (int k8 = 0; k8 < 8; k8++) {
            int kk = jt * 64 + k8 * 8;
            float a0 = sS[(mh + lr) * SLD + kk + lc];
            float a1 = sS[(mh + lr + 8) * SLD + kk + lc];
            float a2 = sS[(mh + lr) * SLD + kk + lc + 4];
            float a3 = sS[(mh + lr + 8) * SLD + kk + lc + 4];
            u32 Ah[4], Al[4];
            split_tf32(a0, Ah[0], Al[0]);
            split_tf32(a1, Ah[1], Al[1]);
            split_tf32(a2, Ah[2], Al[2]);
            split_tf32(a3, Ah[3], Al[3]);
            #pragma unroll
            for (int nt = 0; nt < 2; nt++) {
                int b0i = (k8 * 8 + lc) * VLD + nq + nt * 8 + lr;
                int b1i = (k8 * 8 + lc + 4) * VLD + nq + nt * 8 + lr;
                u32 Bh[2] = { *reinterpret_cast<const u32*>(&sKVh[b0i]),
                              *reinterpret_cast<const u32*>(&sKVh[b1i]) };
                u32 Bl[2] = { *reinterpret_cast<const u32*>(&sKVl[b0i]),
                              *reinterpret_cast<const u32*>(&sKVl[b1i]) };
                mma8(O[nt], Ah, Bh);
                mma8(O[nt], Al, Bh);
                mma8(O[nt], Ah, Bl);
            }
        }
    }

    const int b_ = bh >> 3, h_ = bh & 7;
    float inv0 = sInv[mh + lr], inv1 = sInv[mh + lr + 8];
    #pragma unroll
    for (int nt = 0; nt < 2; nt++) {
        int col = h_ * 64 + nq + nt * 8 + 2 * lc;
        float* o0 = g_heads + ((size_t)(b_ * SN + i0 + mh + lr)) * (HN * DN) + col;
        float* o1 = g_heads + ((size_t)(b_ * SN + i0 + mh + lr + 8)) * (HN * DN) + col;
        *reinterpret_cast<float2*>(o0) = make_float2(O[nt][0] * inv0, O[nt][1] * inv0);
        *reinterpret_cast<float2*>(o1) = make_float2(O[nt][2] * inv1, O[nt][3] * inv1);
    }
}

// ---------------------------------------------------------------------------
// Kernel 4a: proj split-K x8 (unchanged)
// ---------------------------------------------------------------------------
__global__ __launch_bounds__(256) void proj_split_kernel(const float* __restrict__ Wo)
{
    __shared__ float sA[64 * 65];
    __shared__ float sB[64 * 66];
    const int m0 = blockIdx.x * 64;
    const int kb = blockIdx.y * 64;
    const int tid = threadIdx.x;
    const int ty = tid >> 4, tx = tid & 15;

    for (int idx = tid; idx < 64 * 16; idx += 256) {
        int r = idx >> 4, c = (idx & 15) << 2;
        float4 a4 = *reinterpret_cast<const float4*>(
            g_heads + (size_t)(m0 + r) * 512 + kb + c);
        sA[r * 65 + c] = a4.x; sA[r * 65 + c + 1] = a4.y;
        sA[r * 65 + c + 2] = a4.z; sA[r * 65 + c + 3] = a4.w;
        float4 b4 = *reinterpret_cast<const float4*>(
            Wo + (size_t)(kb + r) * 64 + c);
        sB[r * 66 + c] = b4.x; sB[r * 66 + c + 1] = b4.y;
        sB[r * 66 + c + 2] = b4.z; sB[r * 66 + c + 3] = b4.w;
    }
    __syncthreads();

    u64 acc[4][2] = {};
    #pragma unroll 16
    for (int k = 0; k < 64; k++) {
        u64 b0 = *reinterpret_cast<const u64*>(&sB[k * 66 + tx * 4]);
        u64 b1 = *reinterpret_cast<const u64*>(&sB[k * 66 + tx * 4 + 2]);
        #pragma unroll
        for (int i = 0; i < 4; i++) {
            u64 a = dup2(sA[(ty * 4 + i) * 65 + k]);
            ffma2(acc[i][0], a, b0);
            ffma2(acc[i][1], a, b1);
        }
    }

    float* outp = g_po[blockIdx.y];
    #pragma unroll
    for (int i = 0; i < 4; i++) {
        float2 p0 = unpack2(acc[i][0]), p1 = unpack2(acc[i][1]);
        float4 o4 = make_float4(p0.x, p0.y, p1.x, p1.y);
        *reinterpret_cast<float4*>(outp + (size_t)(m0 + ty * 4 + i) * 64 + tx * 4) = o4;
    }
}

// ---------------------------------------------------------------------------
// Kernel 4b v3: 16 rows/block, 4 rows per thread -> 1 weight LDG feeds 4
// independent FFMA2 chains (was 1:1). grid 128.
// ---------------------------------------------------------------------------
__global__ __launch_bounds__(256) void ffn_ln_kernel(
    const float* __restrict__ seq,
    const float* __restrict__ W1, const float* __restrict__ b1,
    const float* __restrict__ W2, const float* __restrict__ b2,
    const float* __restrict__ gam1, const float* __restrict__ bet1,
    const float* __restrict__ gam2, const float* __restrict__ bet2,
    float* __restrict__ out)
{
    __shared__ float sX[16][64];
    __shared__ float sY[16][130];
    __shared__ float sPart[16][64];
    __shared__ float sZ[16][64];
    const int tid = threadIdx.x;
    const int t = tid & 63, rg = tid >> 6;      // rg in [0,4): row group
    const int w = tid >> 5, lane = tid & 31;
    const size_t row0 = (size_t)blockIdx.x * 16;

    // residual + 8 proj partials (raw)
    for (int idx = tid; idx < 1024; idx += 256) {
        int r = idx >> 6, c = idx & 63;
        size_t ro = (row0 + r) * 64 + c;
        float s01 = g_po[0][ro] + g_po[1][ro];
        float s23 = g_po[2][ro] + g_po[3][ro];
        float s45 = g_po[4][ro] + g_po[5][ro];
        float s67 = g_po[6][ro] + g_po[7][ro];
        sX[r][c] = seq[ro] + ((s01 + s23) + (s45 + s67));
    }
    __syncthreads();

    // LN1 in place: warp w -> rows 2w, 2w+1
    #pragma unroll
    for (int rr = 0; rr < 2; rr++) {
        int r = w * 2 + rr;
        float z0 = sX[r][lane], z1 = sX[r][lane + 32];
        float s = z0 + z1, ss = z0 * z0 + z1 * z1;
        #pragma unroll
        for (int off = 16; off > 0; off >>= 1) {
            s  += __shfl_xor_sync(0xffffffffu, s, off);
            ss += __shfl_xor_sync(0xffffffffu, ss, off);
        }
        float mu  = s * (1.f / 64.f);
        float var = ss * (1.f / 64.f) - mu * mu;
        float rs  = rsqrtf(var + EPSV);
        sX[r][lane]      = (z0 - mu) * rs * gam1[lane] + bet1[lane];
        sX[r][lane + 32] = (z1 - mu) * rs * gam1[lane + 32] + bet1[lane + 32];
    }
    __syncthreads();

    // GEMM1: thread (t, rg) computes hidden pair (2t,2t+1) for 4 rows
    {
        u64 a[4];
        u64 binit = *reinterpret_cast<const u64*>(b1 + 2 * t);
        a[0] = a[1] = a[2] = a[3] = binit;
        #pragma unroll 8
        for (int d = 0; d < 64; d++) {
            u64 wv = *reinterpret_cast<const u64*>(W1 + (size_t)d * 128 + 2 * t);
            #pragma unroll
            for (int rr = 0; rr < 4; rr++)
                ffma2(a[rr], dup2(sX[rg * 4 + rr][d]), wv);
        }
        #pragma unroll
        for (int rr = 0; rr < 4; rr++) {
            float2 y = unpack2(a[rr]);
            sY[rg * 4 + rr][2 * t]     = fmaxf(y.x, 0.f);
            sY[rg * 4 + rr][2 * t + 1] = fmaxf(y.y, 0.f);
        }
    }
    __syncthreads();

    // GEMM2: thread (u,g,rg): d-pair (2u,2u+1), f-half g, 4 rows
    const int u = t & 31, g = t >> 5;
    {
        u64 c2[4] = {};
        #pragma unroll 8
        for (int f = 0; f < 64; f++) {
            u64 wv = *reinterpret_cast<const u64*>(W2 + (size_t)(g * 64 + f) * 64 + 2 * u);
            #pragma unroll
            for (int rr = 0; rr < 4; rr++)
                ffma2(c2[rr], dup2(sY[rg * 4 + rr][g * 64 + f]), wv);
        }
        if (g == 1) {
            #pragma unroll
            for (int rr = 0; rr < 4; rr++) {
                float2 p = unpack2(c2[rr]);
                sPart[rg * 4 + rr][2 * u]     = p.x;
                sPart[rg * 4 + rr][2 * u + 1] = p.y;
            }
        }
        __syncthreads();
        if (g == 0) {
            #pragma unroll
            for (int rr = 0; rr < 4; rr++) {
                int r = rg * 4 + rr;
                float2 p = unpack2(c2[rr]);
                sZ[r][2 * u]     = p.x + sPart[r][2 * u]     + b2[2 * u]     + sX[r][2 * u];
                sZ[r][2 * u + 1] = p.y + sPart[r][2 * u + 1] + b2[2 * u + 1] + sX[r][2 * u + 1];
            }
        }
    }
    __syncthreads();

    // LN2: warp w -> rows 2w, 2w+1
    #pragma unroll
    for (int rr = 0; rr < 2; rr++) {
        int r = w * 2 + rr;
        float z0 = sZ[r][lane], z1 = sZ[r][lane + 32];
        float s = z0 + z1, ss = z0 * z0 + z1 * z1;
        #pragma unroll
        for (int off = 16; off > 0; off >>= 1) {
            s  += __shfl_xor_sync(0xffffffffu, s, off);
            ss += __shfl_xor_sync(0xffffffffu, ss, off);
        }
        float mu  = s * (1.f / 64.f);
        float var = ss * (1.f / 64.f) - mu * mu;
        float rs  = rsqrtf(var + EPSV);
        out[(row0 + r) * 64 + lane]      = (z0 - mu) * rs * gam2[lane] + bet2[lane];
        out[(row0 + r) * 64 + lane + 32] = (z1 - mu) * rs * gam2[lane + 32] + bet2[lane + 32];
    }
}

// ---------------------------------------------------------------------------
// Launch
// ---------------------------------------------------------------------------
extern "C" void kernel_launch(void* const* d_in, const int* in_sizes, int n_in,
                              void* d_out, int out_size)
{
    const float* seq   = (const float*)d_in[0];
    const float* pos   = (const float*)d_in[1];
    const float* Wq    = (const float*)d_in[2];
    const float* Wk    = (const float*)d_in[3];
    const float* Wv    = (const float*)d_in[4];
    const float* Wo    = (const float*)d_in[5];
    const float* Wp    = (const float*)d_in[6];
    const float* bp    = (const float*)d_in[7];
    const float* W1    = (const float*)d_in[8];
    const float* b1    = (const float*)d_in[9];
    const float* W2    = (const float*)d_in[10];
    const float* b2    = (const float*)d_in[11];
    const float* g_att = (const float*)d_in[12];
    const float* b_att = (const float*)d_in[13];
    const float* g_ff  = (const float*)d_in[14];
    const float* b_ff  = (const float*)d_in[15];
    float* outp = (float*)d_out;

    cudaFuncSetAttribute(attn_kernel, cudaFuncAttributeMaxDynamicSharedMemorySize,
                         ATTN_SMEM_BYTES);

    prep_kernel<<<PB_BLOCKS + QKV_BLOCKS, 256>>>(seq, Wq, Wk, Wv, pos, Wp, bp);
    attn_kernel<<<dim3(32, 16), 256, ATTN_SMEM_BYTES>>>();
    proj_split_kernel<<<dim3(32, 8), 256>>>(Wo);
    ffn_ln_kernel<<<128, 256>>>(seq, W1, b1, W2, b2, g_att, b_att, g_ff, b_ff, outp);
}

// round 16
// speedup vs baseline: 1.0840x; 1.0840x over previous
#include <cuda_runtime.h>
#include <math.h>

// Problem constants
#define BN   4
#define SN   512
#define DN   64
#define HN   8
#define FFN  128
#define EPSV 1e-5f

typedef unsigned long long u64;
typedef unsigned int u32;

// ---------------------------------------------------------------------------
// Packed fp32x2 helpers (sm_100+)
// ---------------------------------------------------------------------------
__device__ __forceinline__ u64 pack2(float lo, float hi) {
    u64 r; asm("mov.b64 %0, {%1, %2};" : "=l"(r) : "f"(lo), "f"(hi)); return r;
}
__device__ __forceinline__ u64 dup2(float x) {
    u64 r; asm("mov.b64 %0, {%1, %1};" : "=l"(r) : "f"(x)); return r;
}
__device__ __forceinline__ void ffma2(u64& d, u64 a, u64 b) {
    asm("fma.rn.f32x2 %0, %1, %2, %0;" : "+l"(d) : "l"(a), "l"(b));
}
__device__ __forceinline__ u64 addp2(u64 a, u64 b) {
    u64 r; asm("add.rn.f32x2 %0, %1, %2;" : "=l"(r) : "l"(a), "l"(b)); return r;
}
__device__ __forceinline__ float2 unpack2(u64 v) {
    float2 f; asm("mov.b64 {%0, %1}, %2;" : "=f"(f.x), "=f"(f.y) : "l"(v)); return f;
}

// ---------------------------------------------------------------------------
// tf32 MMA helpers
// ---------------------------------------------------------------------------
__device__ __forceinline__ u32 tf32_of(float x) {
    u32 r; asm("cvt.rna.tf32.f32 %0, %1;" : "=r"(r) : "f"(x)); return r;
}
__device__ __forceinline__ void split_tf32(float x, u32& hi, u32& lo) {
    hi = tf32_of(x);
    lo = tf32_of(x - __uint_as_float(hi));
}
__device__ __forceinline__ void mma8(float* d, const u32* a, const u32* b) {
    asm volatile(
        "mma.sync.aligned.m16n8k8.row.col.f32.tf32.tf32.f32 "
        "{%0,%1,%2,%3}, {%4,%5,%6,%7}, {%8,%9}, {%0,%1,%2,%3};"
        : "+f"(d[0]), "+f"(d[1]), "+f"(d[2]), "+f"(d[3])
        : "r"(a[0]), "r"(a[1]), "r"(a[2]), "r"(a[3]), "r"(b[0]), "r"(b[1]));
}

// ---------------------------------------------------------------------------
// Scratch
// ---------------------------------------------------------------------------
__device__ float g_q[BN * HN * SN * DN];
__device__ float g_k[BN * HN * SN * DN];
__device__ float g_v[BN * HN * SN * DN];
__device__ float g_p[(size_t)BN * HN * SN * SN];
__device__ float g_heads[BN * SN * HN * DN];
__device__ float g_po[8][BN * SN * DN];           // proj K-split partials

// ---------------------------------------------------------------------------
// Kernel 1: FUSED posbias + qkv (R13, measured)
// ---------------------------------------------------------------------------
#define PB_BLOCKS (4 * SN * 4)
#define QKV_BLOCKS (32 * 8 * 3)
#define PREP_SMEM_FLOATS (128 * 65 + 64 * 8 + 8)

__global__ __launch_bounds__(256) void prep_kernel(
    const float* __restrict__ seq, const float* __restrict__ Wq,
    const float* __restrict__ Wk, const float* __restrict__ Wv,
    const float* __restrict__ pos, const float* __restrict__ Wp,
    const float* __restrict__ bp)
{
    __shared__ float smem_u[PREP_SMEM_FLOATS];
    const int tid = threadIdx.x;

    if (blockIdx.x < PB_BLOCKS) {
        float (*sP)[65] = reinterpret_cast<float(*)[65]>(smem_u);
        float (*sW)[8]  = reinterpret_cast<float(*)[8]>(smem_u + 128 * 65);
        float* sbp      = smem_u + 128 * 65 + 64 * 8;

        const int idx = blockIdx.x;
        const int jt  = idx & 3;
        const int i   = (idx >> 2) & 511;
        const int b   = idx >> 11;

        for (int k = tid; k < 512; k += 256) sW[k >> 3][k & 7] = Wp[k];
        if (tid < 8) sbp[tid] = bp[tid];

        const float* src = pos + (((size_t)b * SN + i) * SN + jt * 128) * DN;
        #pragma unroll
        for (int it = 0; it < 8; it++) {
            int id = tid + it * 256;
            int r = id >> 4, c = (id & 15) << 2;
            float4 v4 = __ldcs(reinterpret_cast<const float4*>(src + (size_t)r * 64 + c));
            sP[r][c] = v4.x; sP[r][c + 1] = v4.y; sP[r][c + 2] = v4.z; sP[r][c + 3] = v4.w;
        }
        __syncthreads();

        const int jr = tid & 127;
        const int hb = (tid >> 7) * 2;
        u64 acc[2];
        #pragma unroll
        for (int p = 0; p < 2; p++)
            acc[p] = pack2(sbp[2 * (hb + p)], sbp[2 * (hb + p) + 1]);
        #pragma unroll 16
        for (int d = 0; d < 64; d++) {
            u64 x = dup2(sP[jr][d]);
            #pragma unroll
            for (int p = 0; p < 2; p++) {
                u64 w = *reinterpret_cast<const u64*>(&sW[d][2 * (hb + p)]);
                ffma2(acc[p], x, w);
            }
        }

        const int j = jt * 128 + jr;
        #pragma unroll
        for (int p = 0; p < 2; p++) {
            float2 v = unpack2(acc[p]);
            int h0 = 2 * (hb + p);
            g_p[(((size_t)b * HN + h0) * SN + i) * SN + j]     = v.x;
            g_p[(((size_t)b * HN + h0 + 1) * SN + i) * SN + j] = v.y;
        }
    } else {
        float* sA = smem_u;
        float* sB = smem_u + 64 * 65;

        const int bx2  = blockIdx.x - PB_BLOCKS;
        const int m0   = (bx2 & 31) * 64;
        const int head = (bx2 >> 5) & 7;
        const int z    = bx2 >> 8;
        const float* __restrict__ W = (z == 0) ? Wq : (z == 1 ? Wk : Wv);
        float* outB = (z == 0) ? g_q : (z == 1 ? g_k : g_v);

        for (int idx = tid; idx < 64 * 16; idx += 256) {
            int r = idx >> 4, c = (idx & 15) << 2;
            float4 a4 = *reinterpret_cast<const float4*>(seq + (size_t)(m0 + r) * 64 + c);
            sA[r * 65 + c] = a4.x; sA[r * 65 + c + 1] = a4.y;
            sA[r * 65 + c + 2] = a4.z; sA[r * 65 + c + 3] = a4.w;
            float4 b4 = *reinterpret_cast<const float4*>(W + (size_t)r * 512 + head * 64 + c);
            sB[r * 66 + c] = b4.x; sB[r * 66 + c + 1] = b4.y;
            sB[r * 66 + c + 2] = b4.z; sB[r * 66 + c + 3] = b4.w;
        }
        __syncthreads();

        const int ty = tid >> 4, tx = tid & 15;
        u64 acc[4][2] = {};
        #pragma unroll 16
        for (int k = 0; k < 64; k++) {
            u64 b0 = *reinterpret_cast<const u64*>(&sB[k * 66 + tx * 4]);
            u64 b1 = *reinterpret_cast<const u64*>(&sB[k * 66 + tx * 4 + 2]);
            #pragma unroll
            for (int i = 0; i < 4; i++) {
                u64 a = dup2(sA[(ty * 4 + i) * 65 + k]);
                ffma2(acc[i][0], a, b0);
                ffma2(acc[i][1], a, b1);
            }
        }

        const int bb = m0 >> 9;
        const int s0 = m0 & 511;
        #pragma unroll
        for (int i = 0; i < 4; i++) {
            float2 p0 = unpack2(acc[i][0]), p1 = unpack2(acc[i][1]);
            float4 o4 = make_float4(p0.x, p0.y, p1.x, p1.y);
            *reinterpret_cast<float4*>(
                outB + ((size_t)((bb * HN + head) * SN + s0 + ty * 4 + i)) * DN + tx * 4) = o4;
        }
    }
}

// ---------------------------------------------------------------------------
// Kernel 3: attention. Phase 1: 3xTF32 (exact-ish, feeds exp). Phase 3:
// single-rounded tf32 (1 MMA instead of 3, no hi/lo splitting) -- rel_err
// budget is 1e-3, phase-3 rounding lands ~1-3e-4 after downstream dilution.
// K/V register-prefetch pipeline retained.
// ---------------------------------------------------------------------------
#define AT_TI 32
#define QLD   68
#define KLD   68
#define VLD   72
#define SLD   516
#define ATTN_SMEM_FLOATS (AT_TI * QLD + 2 * 64 * VLD + AT_TI * SLD + AT_TI)
#define ATTN_SMEM_BYTES  (ATTN_SMEM_FLOATS * 4)

__global__ __launch_bounds__(256, 2) void attn_kernel()
{
    extern __shared__ float sm[];
    float* sQ   = sm;
    float* sKVh = sQ + AT_TI * QLD;
    float* sKVl = sKVh + 64 * VLD;
    float* sS   = sKVl + 64 * VLD;
    float* sInv = sS + AT_TI * SLD;

    const int bh  = blockIdx.x;
    const int i0  = blockIdx.y * AT_TI;
    const int tid = threadIdx.x;
    const int w    = tid >> 5, lane = tid & 31;
    const int mh   = (w & 1) * 16;
    const int nq   = (w >> 1) * 16;
    const int lr   = lane >> 2, lc = lane & 3;
    const int ldr  = tid >> 4, ldc = (tid & 15) << 2;

    const float* qsrc = g_q + ((size_t)bh * SN + i0) * DN;
    #pragma unroll
    for (int it = 0; it < 2; it++) {
        int id = tid + it * 256;
        int r = id >> 4, c = (id & 15) << 2;
        float4 v = *reinterpret_cast<const float4*>(qsrc + (size_t)r * 64 + c);
        sQ[r * QLD + c] = v.x; sQ[r * QLD + c + 1] = v.y;
        sQ[r * QLD + c + 2] = v.z; sQ[r * QLD + c + 3] = v.w;
    }
    __syncthreads();

    u32 qh[8][4], ql[8][4];
    #pragma unroll
    for (int k8 = 0; k8 < 8; k8++) {
        float a0 = sQ[(mh + lr) * QLD + k8 * 8 + lc];
        float a1 = sQ[(mh + lr + 8) * QLD + k8 * 8 + lc];
        float a2 = sQ[(mh + lr) * QLD + k8 * 8 + lc + 4];
        float a3 = sQ[(mh + lr + 8) * QLD + k8 * 8 + lc + 4];
        split_tf32(a0, qh[k8][0], ql[k8][0]);
        split_tf32(a1, qh[k8][1], ql[k8][1]);
        split_tf32(a2, qh[k8][2], ql[k8][2]);
        split_tf32(a3, qh[k8][3], ql[k8][3]);
    }
    const float* pbase = g_p + ((size_t)bh * SN + i0) * SN;
    const float* kbase = g_k + (size_t)bh * SN * DN;
    const float* vbase = g_v + (size_t)bh * SN * DN;

    // ---- Phase 1: S = QK^T * 0.125 + P  (3xTF32, register-pipelined K)
    float4 kv[4];
    #pragma unroll
    for (int it = 0; it < 4; it++)
        kv[it] = *reinterpret_cast<const float4*>(
            kbase + (size_t)(ldr + it * 16) * 64 + ldc);

    for (int jt = 0; jt < 8; jt++) {
        __syncthreads();
        #pragma unroll
        for (int it = 0; it < 4; it++) {
            int r = ldr + it * 16;
            u32 h0, l0, h1, l1, h2, l2, h3, l3;
            split_tf32(kv[it].x, h0, l0); split_tf32(kv[it].y, h1, l1);
            split_tf32(kv[it].z, h2, l2); split_tf32(kv[it].w, h3, l3);
            *reinterpret_cast<uint4*>(&sKVh[r * KLD + ldc]) = make_uint4(h0, h1, h2, h3);
            *reinterpret_cast<uint4*>(&sKVl[r * KLD + ldc]) = make_uint4(l0, l1, l2, l3);
        }
        __syncthreads();

        if (jt < 7) {
            #pragma unroll
            for (int it = 0; it < 4; it++)
                kv[it] = *reinterpret_cast<const float4*>(
                    kbase + (size_t)((jt + 1) * 64 + ldr + it * 16) * 64 + ldc);
        }

        float2 pf[2][2];
        #pragma unroll
        for (int nt = 0; nt < 2; nt++) {
            int col = jt * 64 + nq + nt * 8 + 2 * lc;
            pf[nt][0] = *reinterpret_cast<const float2*>(
                pbase + (size_t)(mh + lr) * SN + col);
            pf[nt][1] = *reinterpret_cast<const float2*>(
                pbase + (size_t)(mh + lr + 8) * SN + col);
        }

        float D[2][4] = {};
        #pragma unroll
        for (int k8 = 0; k8 < 8; k8++) {
            #pragma unroll
            for (int nt = 0; nt < 2; nt++) {
                int base = (nq + nt * 8 + lr) * KLD + k8 * 8 + lc;
                u32 Bh[2] = { *reinterpret_cast<const u32*>(&sKVh[base]),
                              *reinterpret_cast<const u32*>(&sKVh[base + 4]) };
                u32 Bl[2] = { *reinterpret_cast<const u32*>(&sKVl[base]),
                              *reinterpret_cast<const u32*>(&sKVl[base + 4]) };
                mma8(D[nt], qh[k8], Bh);
                mma8(D[nt], ql[k8], Bh);
                mma8(D[nt], qh[k8], Bl);
            }
        }
        #pragma unroll
        for (int nt = 0; nt < 2; nt++) {
            int col = jt * 64 + nq + nt * 8 + 2 * lc;
            *reinterpret_cast<float2*>(&sS[(mh + lr) * SLD + col]) =
                make_float2(D[nt][0] * 0.125f + pf[nt][0].x,
                            D[nt][1] * 0.125f + pf[nt][0].y);
            *reinterpret_cast<float2*>(&sS[(mh + lr + 8) * SLD + col]) =
                make_float2(D[nt][2] * 0.125f + pf[nt][1].x,
                            D[nt][3] * 0.125f + pf[nt][1].y);
        }
    }
    __syncthreads();

    // ---- Phase 2: softmax
    #pragma unroll
    for (int rr = 0; rr < 4; rr++) {
        int r = w * 4 + rr;
        float* row = sS + r * SLD;
        float mx = -1e30f;
        #pragma unroll
        for (int c = 0; c < 16; c++) mx = fmaxf(mx, row[lane + c * 32]);
        #pragma unroll
        for (int off = 16; off > 0; off >>= 1)
            mx = fmaxf(mx, __shfl_xor_sync(0xffffffffu, mx, off));
        float sum = 0.f;
        #pragma unroll
        for (int c = 0; c < 16; c++) {
            float e = __expf(row[lane + c * 32] - mx);
            row[lane + c * 32] = e;
            sum += e;
        }
        #pragma unroll
        for (int off = 16; off > 0; off >>= 1)
            sum += __shfl_xor_sync(0xffffffffu, sum, off);
        if (lane == 0) sInv[r] = 1.f / sum;
    }
    __syncthreads();

    // ---- Phase 3: O = A @ V  (1xTF32: single-rounded A and V, 1 MMA)
    #pragma unroll
    for (int it = 0; it < 4; it++)
        kv[it] = *reinterpret_cast<const float4*>(
            vbase + (size_t)(ldr + it * 16) * 64 + ldc);

    float O[2][4] = {};
    for (int jt = 0; jt < 8; jt++) {
        __syncthreads();
        #pragma unroll
        for (int it = 0; it < 4; it++) {
            int r = ldr + it * 16;
            *reinterpret_cast<uint4*>(&sKVh[r * VLD + ldc]) =
                make_uint4(tf32_of(kv[it].x), tf32_of(kv[it].y),
                           tf32_of(kv[it].z), tf32_of(kv[it].w));
        }
        __syncthreads();

        if (jt < 7) {
            #pragma unroll
            for (int it = 0; it < 4; it++)
                kv[it] = *reinterpret_cast<const float4*>(
                    vbase + (size_t)((jt + 1) * 64 + ldr + it * 16) * 64 + ldc);
        }

        #pragma unroll
        for (int k8 = 0; k8 < 8; k8++) {
            int kk = jt * 64 + k8 * 8;
            u32 Af[4];
            Af[0] = tf32_of(sS[(mh + lr) * SLD + kk + lc]);
            Af[1] = tf32_of(sS[(mh + lr + 8) * SLD + kk + lc]);
            Af[2] = tf32_of(sS[(mh + lr) * SLD + kk + lc + 4]);
            Af[3] = tf32_of(sS[(mh + lr + 8) * SLD + kk + lc + 4]);
            #pragma unroll
            for (int nt = 0; nt < 2; nt++) {
                u32 Bf[2] = {
                    *reinterpret_cast<const u32*>(&sKVh[(k8 * 8 + lc) * VLD + nq + nt * 8 + lr]),
                    *reinterpret_cast<const u32*>(&sKVh[(k8 * 8 + lc + 4) * VLD + nq + nt * 8 + lr]) };
                mma8(O[nt], Af, Bf);
            }
        }
    }

    const int b_ = bh >> 3, h_ = bh & 7;
    float inv0 = sInv[mh + lr], inv1 = sInv[mh + lr + 8];
    #pragma unroll
    for (int nt = 0; nt < 2; nt++) {
        int col = h_ * 64 + nq + nt * 8 + 2 * lc;
        float* o0 = g_heads + ((size_t)(b_ * SN + i0 + mh + lr)) * (HN * DN) + col;
        float* o1 = g_heads + ((size_t)(b_ * SN + i0 + mh + lr + 8)) * (HN * DN) + col;
        *reinterpret_cast<float2*>(o0) = make_float2(O[nt][0] * inv0, O[nt][1] * inv0);
        *reinterpret_cast<float2*>(o1) = make_float2(O[nt][2] * inv1, O[nt][3] * inv1);
    }
}

// ---------------------------------------------------------------------------
// Kernel 4a: proj split-K x8 (unchanged)
// ---------------------------------------------------------------------------
__global__ __launch_bounds__(256) void proj_split_kernel(const float* __restrict__ Wo)
{
    __shared__ float sA[64 * 65];
    __shared__ float sB[64 * 66];
    const int m0 = blockIdx.x * 64;
    const int kb = blockIdx.y * 64;
    const int tid = threadIdx.x;
    const int ty = tid >> 4, tx = tid & 15;

    for (int idx = tid; idx < 64 * 16; idx += 256) {
        int r = idx >> 4, c = (idx & 15) << 2;
        float4 a4 = *reinterpret_cast<const float4*>(
            g_heads + (size_t)(m0 + r) * 512 + kb + c);
        sA[r * 65 + c] = a4.x; sA[r * 65 + c + 1] = a4.y;
        sA[r * 65 + c + 2] = a4.z; sA[r * 65 + c + 3] = a4.w;
        float4 b4 = *reinterpret_cast<const float4*>(
            Wo + (size_t)(kb + r) * 64 + c);
        sB[r * 66 + c] = b4.x; sB[r * 66 + c + 1] = b4.y;
        sB[r * 66 + c + 2] = b4.z; sB[r * 66 + c + 3] = b4.w;
    }
    __syncthreads();

    u64 acc[4][2] = {};
    #pragma unroll 16
    for (int k = 0; k < 64; k++) {
        u64 b0 = *reinterpret_cast<const u64*>(&sB[k * 66 + tx * 4]);
        u64 b1 = *reinterpret_cast<const u64*>(&sB[k * 66 + tx * 4 + 2]);
        #pragma unroll
        for (int i = 0; i < 4; i++) {
            u64 a = dup2(sA[(ty * 4 + i) * 65 + k]);
            ffma2(acc[i][0], a, b0);
            ffma2(acc[i][1], a, b1);
        }
    }

    float* outp = g_po[blockIdx.y];
    #pragma unroll
    for (int i = 0; i < 4; i++) {
        float2 p0 = unpack2(acc[i][0]), p1 = unpack2(acc[i][1]);
        float4 o4 = make_float4(p0.x, p0.y, p1.x, p1.y);
        *reinterpret_cast<float4*>(outp + (size_t)(m0 + ty * 4 + i) * 64 + tx * 4) = o4;
    }
}

// ---------------------------------------------------------------------------
// Kernel 4b: R13 version (grid 512, 4 rows/block -- measured 19.3us; the
// R15 16-row variant regressed to 20.7 at occ 11.7%).
// ---------------------------------------------------------------------------
__global__ __launch_bounds__(256) void ffn_ln_kernel(
    const float* __restrict__ seq,
    const float* __restrict__ W1, const float* __restrict__ b1,
    const float* __restrict__ W2, const float* __restrict__ b2,
    const float* __restrict__ gam1, const float* __restrict__ bet1,
    const float* __restrict__ gam2, const float* __restrict__ bet2,
    float* __restrict__ out)
{
    __shared__ float sRes[4][64];
    __shared__ float sX[4][64];
    __shared__ float sY[4][128];
    __shared__ float sPp[4][64];
    __shared__ float sZ[4][64];
    const int tid  = threadIdx.x;
    const int r4   = tid >> 6;
    const int t    = tid & 63;
    const size_t row = (size_t)blockIdx.x * 4 + r4;
    const size_t ro = row * 64 + t;

    {
        float s01 = g_po[0][ro] + g_po[1][ro];
        float s23 = g_po[2][ro] + g_po[3][ro];
        float s45 = g_po[4][ro] + g_po[5][ro];
        float s67 = g_po[6][ro] + g_po[7][ro];
        sRes[r4][t] = seq[ro] + ((s01 + s23) + (s45 + s67));
    }
    __syncthreads();

    const int u = t & 31, g = t >> 5;
    if (g == 0) {   // LN1
        float z0 = sRes[r4][u], z1 = sRes[r4][u + 32];
        float s = z0 + z1, ss = z0 * z0 + z1 * z1;
        #pragma unroll
        for (int off = 16; off > 0; off >>= 1) {
            s  += __shfl_xor_sync(0xffffffffu, s, off);
            ss += __shfl_xor_sync(0xffffffffu, ss, off);
        }
        float mu  = s * (1.f / 64.f);
        float var = ss * (1.f / 64.f) - mu * mu;
        float rs  = rsqrtf(var + EPSV);
        sX[r4][u]      = (z0 - mu) * rs * gam1[u] + bet1[u];
        sX[r4][u + 32] = (z1 - mu) * rs * gam1[u + 32] + bet1[u + 32];
    }
    __syncthreads();

    u64 a1a = *reinterpret_cast<const u64*>(b1 + 2 * t), a1b = 0;
    #pragma unroll 16
    for (int d = 0; d < 64; d += 2) {
        u64 w0 = *reinterpret_cast<const u64*>(W1 + (size_t)d * 128 + 2 * t);
        u64 w1 = *reinterpret_cast<const u64*>(W1 + (size_t)(d + 1) * 128 + 2 * t);
        ffma2(a1a, dup2(sX[r4][d]), w0);
        ffma2(a1b, dup2(sX[r4][d + 1]), w1);
    }
    {
        float2 y = unpack2(addp2(a1a, a1b));
        sY[r4][2 * t]     = fmaxf(y.x, 0.f);
        sY[r4][2 * t + 1] = fmaxf(y.y, 0.f);
    }
    __syncthreads();

    u64 a2a = 0, a2b = 0;
    #pragma unroll 16
    for (int f = 0; f < 64; f += 2) {
        u64 w0 = *reinterpret_cast<const u64*>(W2 + (size_t)(g * 64 + f) * 64 + 2 * u);
        u64 w1 = *reinterpret_cast<const u64*>(W2 + (size_t)(g * 64 + f + 1) * 64 + 2 * u);
        ffma2(a2a, dup2(sY[r4][g * 64 + f]), w0);
        ffma2(a2b, dup2(sY[r4][g * 64 + f + 1]), w1);
    }
    float2 p = unpack2(addp2(a2a, a2b));
    if (g == 1) { sPp[r4][2 * u] = p.x; sPp[r4][2 * u + 1] = p.y; }
    __syncthreads();
    if (g == 0) {
        sZ[r4][2 * u]     = p.x + sPp[r4][2 * u]     + b2[2 * u]     + sX[r4][2 * u];
        sZ[r4][2 * u + 1] = p.y + sPp[r4][2 * u + 1] + b2[2 * u + 1] + sX[r4][2 * u + 1];
    }
    __syncthreads();

    if (g == 0) {   // LN2
        float z0 = sZ[r4][u], z1 = sZ[r4][u + 32];
        float s = z0 + z1, ss = z0 * z0 + z1 * z1;
        #pragma unroll
        for (int off = 16; off > 0; off >>= 1) {
            s  += __shfl_xor_sync(0xffffffffu, s, off);
            ss += __shfl_xor_sync(0xffffffffu, ss, off);
        }
        float mu  = s * (1.f / 64.f);
        float var = ss * (1.f / 64.f) - mu * mu;
        float rs  = rsqrtf(var + EPSV);
        out[row * 64 + u]      = (z0 - mu) * rs * gam2[u] + bet2[u];
        out[row * 64 + u + 32] = (z1 - mu) * rs * gam2[u + 32] + bet2[u + 32];
    }
}

// ---------------------------------------------------------------------------
// Launch
// ---------------------------------------------------------------------------
extern "C" void kernel_launch(void* const* d_in, const int* in_sizes, int n_in,
                              void* d_out, int out_size)
{
    const float* seq   = (const float*)d_in[0];
    const float* pos   = (const float*)d_in[1];
    const float* Wq    = (const float*)d_in[2];
    const float* Wk    = (const float*)d_in[3];
    const float* Wv    = (const float*)d_in[4];
    const float* Wo    = (const float*)d_in[5];
    const float* Wp    = (const float*)d_in[6];
    const float* bp    = (const float*)d_in[7];
    const float* W1    = (const float*)d_in[8];
    const float* b1    = (const float*)d_in[9];
    const float* W2    = (const float*)d_in[10];
    const float* b2    = (const float*)d_in[11];
    const float* g_att = (const float*)d_in[12];
    const float* b_att = (const float*)d_in[13];
    const float* g_ff  = (const float*)d_in[14];
    const float* b_ff  = (const float*)d_in[15];
    float* outp = (float*)d_out;

    cudaFuncSetAttribute(attn_kernel, cudaFuncAttributeMaxDynamicSharedMemorySize,
                         ATTN_SMEM_BYTES);

    prep_kernel<<<PB_BLOCKS + QKV_BLOCKS, 256>>>(seq, Wq, Wk, Wv, pos, Wp, bp);
    attn_kernel<<<dim3(32, 16), 256, ATTN_SMEM_BYTES>>>();
    proj_split_kernel<<<dim3(32, 8), 256>>>(Wo);
    ffn_ln_kernel<<<512, 256>>>(seq, W1, b1, W2, b2, g_att, b_att, g_ff, b_ff, outp);
}

// round 17
// speedup vs baseline: 1.1503x; 1.0611x over previous
#include <cuda_runtime.h>
#include <math.h>

// Problem constants
#define BN   4
#define SN   512
#define DN   64
#define HN   8
#define FFN  128
#define EPSV 1e-5f

typedef unsigned long long u64;
typedef unsigned int u32;

// ---------------------------------------------------------------------------
// Packed fp32x2 helpers (sm_100+)
// ---------------------------------------------------------------------------
__device__ __forceinline__ u64 pack2(float lo, float hi) {
    u64 r; asm("mov.b64 %0, {%1, %2};" : "=l"(r) : "f"(lo), "f"(hi)); return r;
}
__device__ __forceinline__ u64 dup2(float x) {
    u64 r; asm("mov.b64 %0, {%1, %1};" : "=l"(r) : "f"(x)); return r;
}
__device__ __forceinline__ void ffma2(u64& d, u64 a, u64 b) {
    asm("fma.rn.f32x2 %0, %1, %2, %0;" : "+l"(d) : "l"(a), "l"(b));
}
__device__ __forceinline__ u64 addp2(u64 a, u64 b) {
    u64 r; asm("add.rn.f32x2 %0, %1, %2;" : "=l"(r) : "l"(a), "l"(b)); return r;
}
__device__ __forceinline__ float2 unpack2(u64 v) {
    float2 f; asm("mov.b64 {%0, %1}, %2;" : "=f"(f.x), "=f"(f.y) : "l"(v)); return f;
}

// ---------------------------------------------------------------------------
// tf32 MMA helpers
// ---------------------------------------------------------------------------
__device__ __forceinline__ u32 tf32_of(float x) {
    u32 r; asm("cvt.rna.tf32.f32 %0, %1;" : "=r"(r) : "f"(x)); return r;
}
__device__ __forceinline__ void split_tf32(float x, u32& hi, u32& lo) {
    hi = tf32_of(x);
    lo = tf32_of(x - __uint_as_float(hi));
}
__device__ __forceinline__ void mma8(float* d, const u32* a, const u32* b) {
    asm volatile(
        "mma.sync.aligned.m16n8k8.row.col.f32.tf32.tf32.f32 "
        "{%0,%1,%2,%3}, {%4,%5,%6,%7}, {%8,%9}, {%0,%1,%2,%3};"
        : "+f"(d[0]), "+f"(d[1]), "+f"(d[2]), "+f"(d[3])
        : "r"(a[0]), "r"(a[1]), "r"(a[2]), "r"(a[3]), "r"(b[0]), "r"(b[1]));
}

// ---------------------------------------------------------------------------
// Scratch
// ---------------------------------------------------------------------------
__device__ float g_q[BN * HN * SN * DN];
__device__ float g_k[BN * HN * SN * DN];
__device__ float g_v[BN * HN * SN * DN];
__device__ float g_p[(size_t)BN * HN * SN * SN];
__device__ float g_heads[BN * SN * HN * DN];
__device__ float g_po[8][BN * SN * DN];           // proj K-split partials

// ---------------------------------------------------------------------------
// Kernel 1: FUSED posbias + qkv (R13, measured)
// ---------------------------------------------------------------------------
#define PB_BLOCKS (4 * SN * 4)
#define QKV_BLOCKS (32 * 8 * 3)
#define PREP_SMEM_FLOATS (128 * 65 + 64 * 8 + 8)

__global__ __launch_bounds__(256) void prep_kernel(
    const float* __restrict__ seq, const float* __restrict__ Wq,
    const float* __restrict__ Wk, const float* __restrict__ Wv,
    const float* __restrict__ pos, const float* __restrict__ Wp,
    const float* __restrict__ bp)
{
    __shared__ float smem_u[PREP_SMEM_FLOATS];
    const int tid = threadIdx.x;

    if (blockIdx.x < PB_BLOCKS) {
        float (*sP)[65] = reinterpret_cast<float(*)[65]>(smem_u);
        float (*sW)[8]  = reinterpret_cast<float(*)[8]>(smem_u + 128 * 65);
        float* sbp      = smem_u + 128 * 65 + 64 * 8;

        const int idx = blockIdx.x;
        const int jt  = idx & 3;
        const int i   = (idx >> 2) & 511;
        const int b   = idx >> 11;

        for (int k = tid; k < 512; k += 256) sW[k >> 3][k & 7] = Wp[k];
        if (tid < 8) sbp[tid] = bp[tid];

        const float* src = pos + (((size_t)b * SN + i) * SN + jt * 128) * DN;
        #pragma unroll
        for (int it = 0; it < 8; it++) {
            int id = tid + it * 256;
            int r = id >> 4, c = (id & 15) << 2;
            float4 v4 = __ldcs(reinterpret_cast<const float4*>(src + (size_t)r * 64 + c));
            sP[r][c] = v4.x; sP[r][c + 1] = v4.y; sP[r][c + 2] = v4.z; sP[r][c + 3] = v4.w;
        }
        __syncthreads();

        const int jr = tid & 127;
        const int hb = (tid >> 7) * 2;
        u64 acc[2];
        #pragma unroll
        for (int p = 0; p < 2; p++)
            acc[p] = pack2(sbp[2 * (hb + p)], sbp[2 * (hb + p) + 1]);
        #pragma unroll 16
        for (int d = 0; d < 64; d++) {
            u64 x = dup2(sP[jr][d]);
            #pragma unroll
            for (int p = 0; p < 2; p++) {
                u64 w = *reinterpret_cast<const u64*>(&sW[d][2 * (hb + p)]);
                ffma2(acc[p], x, w);
            }
        }

        const int j = jt * 128 + jr;
        #pragma unroll
        for (int p = 0; p < 2; p++) {
            float2 v = unpack2(acc[p]);
            int h0 = 2 * (hb + p);
            g_p[(((size_t)b * HN + h0) * SN + i) * SN + j]     = v.x;
            g_p[(((size_t)b * HN + h0 + 1) * SN + i) * SN + j] = v.y;
        }
    } else {
        float* sA = smem_u;
        float* sB = smem_u + 64 * 65;

        const int bx2  = blockIdx.x - PB_BLOCKS;
        const int m0   = (bx2 & 31) * 64;
        const int head = (bx2 >> 5) & 7;
        const int z    = bx2 >> 8;
        const float* __restrict__ W = (z == 0) ? Wq : (z == 1 ? Wk : Wv);
        float* outB = (z == 0) ? g_q : (z == 1 ? g_k : g_v);

        for (int idx = tid; idx < 64 * 16; idx += 256) {
            int r = idx >> 4, c = (idx & 15) << 2;
            float4 a4 = *reinterpret_cast<const float4*>(seq + (size_t)(m0 + r) * 64 + c);
            sA[r * 65 + c] = a4.x; sA[r * 65 + c + 1] = a4.y;
            sA[r * 65 + c + 2] = a4.z; sA[r * 65 + c + 3] = a4.w;
            float4 b4 = *reinterpret_cast<const float4*>(W + (size_t)r * 512 + head * 64 + c);
            sB[r * 66 + c] = b4.x; sB[r * 66 + c + 1] = b4.y;
            sB[r * 66 + c + 2] = b4.z; sB[r * 66 + c + 3] = b4.w;
        }
        __syncthreads();

        const int ty = tid >> 4, tx = tid & 15;
        u64 acc[4][2] = {};
        #pragma unroll 16
        for (int k = 0; k < 64; k++) {
            u64 b0 = *reinterpret_cast<const u64*>(&sB[k * 66 + tx * 4]);
            u64 b1 = *reinterpret_cast<const u64*>(&sB[k * 66 + tx * 4 + 2]);
            #pragma unroll
            for (int i = 0; i < 4; i++) {
                u64 a = dup2(sA[(ty * 4 + i) * 65 + k]);
                ffma2(acc[i][0], a, b0);
                ffma2(acc[i][1], a, b1);
            }
        }

        const int bb = m0 >> 9;
        const int s0 = m0 & 511;
        #pragma unroll
        for (int i = 0; i < 4; i++) {
            float2 p0 = unpack2(acc[i][0]), p1 = unpack2(acc[i][1]);
            float4 o4 = make_float4(p0.x, p0.y, p1.x, p1.y);
            *reinterpret_cast<float4*>(
                outB + ((size_t)((bb * HN + head) * SN + s0 + ty * 4 + i)) * DN + tx * 4) = o4;
        }
    }
}

// ---------------------------------------------------------------------------
// Kernel 3: attention. Phase 1: Q exact (hi/lo split, amortized over jts),
// K single-rounded tf32 -> 2 MMAs/fragment (error ~1e-4, budget 1e-3).
// Phase 3: 1xTF32 (measured safe at 3.2e-5 in R16). One KV smem array.
// smem: sQ[32][68] | sKV[64][72] | sS[32][516] = 93.3 KB -> 2 CTAs/SM.
// ---------------------------------------------------------------------------
#define AT_TI 32
#define QLD   68
#define KLD   68
#define VLD   72
#define SLD   516
#define ATTN_SMEM_FLOATS (AT_TI * QLD + 64 * VLD + AT_TI * SLD + AT_TI)
#define ATTN_SMEM_BYTES  (ATTN_SMEM_FLOATS * 4)

__global__ __launch_bounds__(256, 2) void attn_kernel()
{
    extern __shared__ float sm[];
    float* sQ   = sm;
    float* sKV  = sQ + AT_TI * QLD;
    float* sS   = sKV + 64 * VLD;
    float* sInv = sS + AT_TI * SLD;

    const int bh  = blockIdx.x;
    const int i0  = blockIdx.y * AT_TI;
    const int tid = threadIdx.x;
    const int w    = tid >> 5, lane = tid & 31;
    const int mh   = (w & 1) * 16;
    const int nq   = (w >> 1) * 16;
    const int lr   = lane >> 2, lc = lane & 3;
    const int ldr  = tid >> 4, ldc = (tid & 15) << 2;

    const float* qsrc = g_q + ((size_t)bh * SN + i0) * DN;
    #pragma unroll
    for (int it = 0; it < 2; it++) {
        int id = tid + it * 256;
        int r = id >> 4, c = (id & 15) << 2;
        float4 v = *reinterpret_cast<const float4*>(qsrc + (size_t)r * 64 + c);
        sQ[r * QLD + c] = v.x; sQ[r * QLD + c + 1] = v.y;
        sQ[r * QLD + c + 2] = v.z; sQ[r * QLD + c + 3] = v.w;
    }
    __syncthreads();

    u32 qh[8][4], ql[8][4];
    #pragma unroll
    for (int k8 = 0; k8 < 8; k8++) {
        float a0 = sQ[(mh + lr) * QLD + k8 * 8 + lc];
        float a1 = sQ[(mh + lr + 8) * QLD + k8 * 8 + lc];
        float a2 = sQ[(mh + lr) * QLD + k8 * 8 + lc + 4];
        float a3 = sQ[(mh + lr + 8) * QLD + k8 * 8 + lc + 4];
        split_tf32(a0, qh[k8][0], ql[k8][0]);
        split_tf32(a1, qh[k8][1], ql[k8][1]);
        split_tf32(a2, qh[k8][2], ql[k8][2]);
        split_tf32(a3, qh[k8][3], ql[k8][3]);
    }
    const float* pbase = g_p + ((size_t)bh * SN + i0) * SN;
    const float* kbase = g_k + (size_t)bh * SN * DN;
    const float* vbase = g_v + (size_t)bh * SN * DN;

    // ---- Phase 1: S = QK^T * 0.125 + P  (K single tf32, 2 MMAs)
    float4 kv[4];
    #pragma unroll
    for (int it = 0; it < 4; it++)
        kv[it] = *reinterpret_cast<const float4*>(
            kbase + (size_t)(ldr + it * 16) * 64 + ldc);

    for (int jt = 0; jt < 8; jt++) {
        __syncthreads();
        #pragma unroll
        for (int it = 0; it < 4; it++) {
            int r = ldr + it * 16;
            *reinterpret_cast<uint4*>(&sKV[r * KLD + ldc]) =
                make_uint4(tf32_of(kv[it].x), tf32_of(kv[it].y),
                           tf32_of(kv[it].z), tf32_of(kv[it].w));
        }
        __syncthreads();

        if (jt < 7) {
            #pragma unroll
            for (int it = 0; it < 4; it++)
                kv[it] = *reinterpret_cast<const float4*>(
                    kbase + (size_t)((jt + 1) * 64 + ldr + it * 16) * 64 + ldc);
        }

        float2 pf[2][2];
        #pragma unroll
        for (int nt = 0; nt < 2; nt++) {
            int col = jt * 64 + nq + nt * 8 + 2 * lc;
            pf[nt][0] = *reinterpret_cast<const float2*>(
                pbase + (size_t)(mh + lr) * SN + col);
            pf[nt][1] = *reinterpret_cast<const float2*>(
                pbase + (size_t)(mh + lr + 8) * SN + col);
        }

        float D[2][4] = {};
        #pragma unroll
        for (int k8 = 0; k8 < 8; k8++) {
            #pragma unroll
            for (int nt = 0; nt < 2; nt++) {
                int base = (nq + nt * 8 + lr) * KLD + k8 * 8 + lc;
                u32 Bf[2] = { *reinterpret_cast<const u32*>(&sKV[base]),
                              *reinterpret_cast<const u32*>(&sKV[base + 4]) };
                mma8(D[nt], qh[k8], Bf);
                mma8(D[nt], ql[k8], Bf);
            }
        }
        #pragma unroll
        for (int nt = 0; nt < 2; nt++) {
            int col = jt * 64 + nq + nt * 8 + 2 * lc;
            *reinterpret_cast<float2*>(&sS[(mh + lr) * SLD + col]) =
                make_float2(D[nt][0] * 0.125f + pf[nt][0].x,
                            D[nt][1] * 0.125f + pf[nt][0].y);
            *reinterpret_cast<float2*>(&sS[(mh + lr + 8) * SLD + col]) =
                make_float2(D[nt][2] * 0.125f + pf[nt][1].x,
                            D[nt][3] * 0.125f + pf[nt][1].y);
        }
    }
    __syncthreads();

    // ---- Phase 2: softmax
    #pragma unroll
    for (int rr = 0; rr < 4; rr++) {
        int r = w * 4 + rr;
        float* row = sS + r * SLD;
        float mx = -1e30f;
        #pragma unroll
        for (int c = 0; c < 16; c++) mx = fmaxf(mx, row[lane + c * 32]);
        #pragma unroll
        for (int off = 16; off > 0; off >>= 1)
            mx = fmaxf(mx, __shfl_xor_sync(0xffffffffu, mx, off));
        float sum = 0.f;
        #pragma unroll
        for (int c = 0; c < 16; c++) {
            float e = __expf(row[lane + c * 32] - mx);
            row[lane + c * 32] = e;
            sum += e;
        }
        #pragma unroll
        for (int off = 16; off > 0; off >>= 1)
            sum += __shfl_xor_sync(0xffffffffu, sum, off);
        if (lane == 0) sInv[r] = 1.f / sum;
    }
    __syncthreads();

    // ---- Phase 3: O = A @ V  (1xTF32, measured safe)
    #pragma unroll
    for (int it = 0; it < 4; it++)
        kv[it] = *reinterpret_cast<const float4*>(
            vbase + (size_t)(ldr + it * 16) * 64 + ldc);

    float O[2][4] = {};
    for (int jt = 0; jt < 8; jt++) {
        __syncthreads();
        #pragma unroll
        for (int it = 0; it < 4; it++) {
            int r = ldr + it * 16;
            *reinterpret_cast<uint4*>(&sKV[r * VLD + ldc]) =
                make_uint4(tf32_of(kv[it].x), tf32_of(kv[it].y),
                           tf32_of(kv[it].z), tf32_of(kv[it].w));
        }
        __syncthreads();

        if (jt < 7) {
            #pragma unroll
            for (int it = 0; it < 4; it++)
                kv[it] = *reinterpret_cast<const float4*>(
                    vbase + (size_t)((jt + 1) * 64 + ldr + it * 16) * 64 + ldc);
        }

        #pragma unroll
        for (int k8 = 0; k8 < 8; k8++) {
            int kk = jt * 64 + k8 * 8;
            u32 Af[4];
            Af[0] = tf32_of(sS[(mh + lr) * SLD + kk + lc]);
            Af[1] = tf32_of(sS[(mh + lr + 8) * SLD + kk + lc]);
            Af[2] = tf32_of(sS[(mh + lr) * SLD + kk + lc + 4]);
            Af[3] = tf32_of(sS[(mh + lr + 8) * SLD + kk + lc + 4]);
            #pragma unroll
            for (int nt = 0; nt < 2; nt++) {
                u32 Bf[2] = {
                    *reinterpret_cast<const u32*>(&sKV[(k8 * 8 + lc) * VLD + nq + nt * 8 + lr]),
                    *reinterpret_cast<const u32*>(&sKV[(k8 * 8 + lc + 4) * VLD + nq + nt * 8 + lr]) };
                mma8(O[nt], Af, Bf);
            }
        }
    }

    const int b_ = bh >> 3, h_ = bh & 7;
    float inv0 = sInv[mh + lr], inv1 = sInv[mh + lr + 8];
    #pragma unroll
    for (int nt = 0; nt < 2; nt++) {
        int col = h_ * 64 + nq + nt * 8 + 2 * lc;
        float* o0 = g_heads + ((size_t)(b_ * SN + i0 + mh + lr)) * (HN * DN) + col;
        float* o1 = g_heads + ((size_t)(b_ * SN + i0 + mh + lr + 8)) * (HN * DN) + col;
        *reinterpret_cast<float2*>(o0) = make_float2(O[nt][0] * inv0, O[nt][1] * inv0);
        *reinterpret_cast<float2*>(o1) = make_float2(O[nt][2] * inv1, O[nt][3] * inv1);
    }
}

// ---------------------------------------------------------------------------
// Kernel 4a: proj split-K x8 (unchanged)
// ---------------------------------------------------------------------------
__global__ __launch_bounds__(256) void proj_split_kernel(const float* __restrict__ Wo)
{
    __shared__ float sA[64 * 65];
    __shared__ float sB[64 * 66];
    const int m0 = blockIdx.x * 64;
    const int kb = blockIdx.y * 64;
    const int tid = threadIdx.x;
    const int ty = tid >> 4, tx = tid & 15;

    for (int idx = tid; idx < 64 * 16; idx += 256) {
        int r = idx >> 4, c = (idx & 15) << 2;
        float4 a4 = *reinterpret_cast<const float4*>(
            g_heads + (size_t)(m0 + r) * 512 + kb + c);
        sA[r * 65 + c] = a4.x; sA[r * 65 + c + 1] = a4.y;
        sA[r * 65 + c + 2] = a4.z; sA[r * 65 + c + 3] = a4.w;
        float4 b4 = *reinterpret_cast<const float4*>(
            Wo + (size_t)(kb + r) * 64 + c);
        sB[r * 66 + c] = b4.x; sB[r * 66 + c + 1] = b4.y;
        sB[r * 66 + c + 2] = b4.z; sB[r * 66 + c + 3] = b4.w;
    }
    __syncthreads();

    u64 acc[4][2] = {};
    #pragma unroll 16
    for (int k = 0; k < 64; k++) {
        u64 b0 = *reinterpret_cast<const u64*>(&sB[k * 66 + tx * 4]);
        u64 b1 = *reinterpret_cast<const u64*>(&sB[k * 66 + tx * 4 + 2]);
        #pragma unroll
        for (int i = 0; i < 4; i++) {
            u64 a = dup2(sA[(ty * 4 + i) * 65 + k]);
            ffma2(acc[i][0], a, b0);
            ffma2(acc[i][1], a, b1);
        }
    }

    float* outp = g_po[blockIdx.y];
    #pragma unroll
    for (int i = 0; i < 4; i++) {
        float2 p0 = unpack2(acc[i][0]), p1 = unpack2(acc[i][1]);
        float4 o4 = make_float4(p0.x, p0.y, p1.x, p1.y);
        *reinterpret_cast<float4*>(outp + (size_t)(m0 + ty * 4 + i) * 64 + tx * 4) = o4;
    }
}

// ---------------------------------------------------------------------------
// Kernel 4b: R13/R16 version (grid 512, 4 rows/block -- measured 18.9us)
// ---------------------------------------------------------------------------
__global__ __launch_bounds__(256) void ffn_ln_kernel(
    const float* __restrict__ seq,
    const float* __restrict__ W1, const float* __restrict__ b1,
    const float* __restrict__ W2, const float* __restrict__ b2,
    const float* __restrict__ gam1, const float* __restrict__ bet1,
    const float* __restrict__ gam2, const float* __restrict__ bet2,
    float* __restrict__ out)
{
    __shared__ float sRes[4][64];
    __shared__ float sX[4][64];
    __shared__ float sY[4][128];
    __shared__ float sPp[4][64];
    __shared__ float sZ[4][64];
    const int tid  = threadIdx.x;
    const int r4   = tid >> 6;
    const int t    = tid & 63;
    const size_t row = (size_t)blockIdx.x * 4 + r4;
    const size_t ro = row * 64 + t;

    {
        float s01 = g_po[0][ro] + g_po[1][ro];
        float s23 = g_po[2][ro] + g_po[3][ro];
        float s45 = g_po[4][ro] + g_po[5][ro];
        float s67 = g_po[6][ro] + g_po[7][ro];
        sRes[r4][t] = seq[ro] + ((s01 + s23) + (s45 + s67));
    }
    __syncthreads();

    const int u = t & 31, g = t >> 5;
    if (g == 0) {   // LN1
        float z0 = sRes[r4][u], z1 = sRes[r4][u + 32];
        float s = z0 + z1, ss = z0 * z0 + z1 * z1;
        #pragma unroll
        for (int off = 16; off > 0; off >>= 1) {
            s  += __shfl_xor_sync(0xffffffffu, s, off);
            ss += __shfl_xor_sync(0xffffffffu, ss, off);
        }
        float mu  = s * (1.f / 64.f);
        float var = ss * (1.f / 64.f) - mu * mu;
        float rs  = rsqrtf(var + EPSV);
        sX[r4][u]      = (z0 - mu) * rs * gam1[u] + bet1[u];
        sX[r4][u + 32] = (z1 - mu) * rs * gam1[u + 32] + bet1[u + 32];
    }
    __syncthreads();

    u64 a1a = *reinterpret_cast<const u64*>(b1 + 2 * t), a1b = 0;
    #pragma unroll 16
    for (int d = 0; d < 64; d += 2) {
        u64 w0 = *reinterpret_cast<const u64*>(W1 + (size_t)d * 128 + 2 * t);
        u64 w1 = *reinterpret_cast<const u64*>(W1 + (size_t)(d + 1) * 128 + 2 * t);
        ffma2(a1a, dup2(sX[r4][d]), w0);
        ffma2(a1b, dup2(sX[r4][d + 1]), w1);
    }
    {
        float2 y = unpack2(addp2(a1a, a1b));
        sY[r4][2 * t]     = fmaxf(y.x, 0.f);
        sY[r4][2 * t + 1] = fmaxf(y.y, 0.f);
    }
    __syncthreads();

    u64 a2a = 0, a2b = 0;
    #pragma unroll 16
    for (int f = 0; f < 64; f += 2) {
        u64 w0 = *reinterpret_cast<const u64*>(W2 + (size_t)(g * 64 + f) * 64 + 2 * u);
        u64 w1 = *reinterpret_cast<const u64*>(W2 + (size_t)(g * 64 + f + 1) * 64 + 2 * u);
        ffma2(a2a, dup2(sY[r4][g * 64 + f]), w0);
        ffma2(a2b, dup2(sY[r4][g * 64 + f + 1]), w1);
    }
    float2 p = unpack2(addp2(a2a, a2b));
    if (g == 1) { sPp[r4][2 * u] = p.x; sPp[r4][2 * u + 1] = p.y; }
    __syncthreads();
    if (g == 0) {
        sZ[r4][2 * u]     = p.x + sPp[r4][2 * u]     + b2[2 * u]     + sX[r4][2 * u];
        sZ[r4][2 * u + 1] = p.y + sPp[r4][2 * u + 1] + b2[2 * u + 1] + sX[r4][2 * u + 1];
    }
    __syncthreads();

    if (g == 0) {   // LN2
        float z0 = sZ[r4][u], z1 = sZ[r4][u + 32];
        float s = z0 + z1, ss = z0 * z0 + z1 * z1;
        #pragma unroll
        for (int off = 16; off > 0; off >>= 1) {
            s  += __shfl_xor_sync(0xffffffffu, s, off);
            ss += __shfl_xor_sync(0xffffffffu, ss, off);
        }
        float mu  = s * (1.f / 64.f);
        float var = ss * (1.f / 64.f) - mu * mu;
        float rs  = rsqrtf(var + EPSV);
        out[row * 64 + u]      = (z0 - mu) * rs * gam2[u] + bet2[u];
        out[row * 64 + u + 32] = (z1 - mu) * rs * gam2[u + 32] + bet2[u + 32];
    }
}

// ---------------------------------------------------------------------------
// Launch
// ---------------------------------------------------------------------------
extern "C" void kernel_launch(void* const* d_in, const int* in_sizes, int n_in,
                              void* d_out, int out_size)
{
    const float* seq   = (const float*)d_in[0];
    const float* pos   = (const float*)d_in[1];
    const float* Wq    = (const float*)d_in[2];
    const float* Wk    = (const float*)d_in[3];
    const float* Wv    = (const float*)d_in[4];
    const float* Wo    = (const float*)d_in[5];
    const float* Wp    = (const float*)d_in[6];
    const float* bp    = (const float*)d_in[7];
    const float* W1    = (const float*)d_in[8];
    const float* b1    = (const float*)d_in[9];
    const float* W2    = (const float*)d_in[10];
    const float* b2    = (const float*)d_in[11];
    const float* g_att = (const float*)d_in[12];
    const float* b_att = (const float*)d_in[13];
    const float* g_ff  = (const float*)d_in[14];
    const float* b_ff  = (const float*)d_in[15];
    float* outp = (float*)d_out;

    cudaFuncSetAttribute(attn_kernel, cudaFuncAttributeMaxDynamicSharedMemorySize,
                         ATTN_SMEM_BYTES);

    prep_kernel<<<PB_BLOCKS + QKV_BLOCKS, 256>>>(seq, Wq, Wk, Wv, pos, Wp, bp);
    attn_kernel<<<dim3(32, 16), 256, ATTN_SMEM_BYTES>>>();
    proj_split_kernel<<<dim3(32, 8), 256>>>(Wo);
    ffn_ln_kernel<<<512, 256>>>(seq, W1, b1, W2, b2, g_att, b_att, g_ff, b_ff, outp);
}